// round 10
// baseline (speedup 1.0000x reference)
#include <cuda_runtime.h>
#include <cuda_fp16.h>
#include <cuda_bf16.h>

// Shapes (fixed for this problem): B=4, V=20000, D=64, R=64, E=640000
#define Bc   4
#define Dc   64
#define Rc   64
#define BD   256          // B*D
#define VMAX 20000
#define EMAX 640000
#define LN_EPS 1e-5f
#define PGRID 296         // prep/agg grid; all-resident (2 blocks/SM)

// ---------------- device scratch (no allocations allowed) ----------------
__device__ float  g_rel[Rc * BD];            // relation[r][b*64+d] (64 KB, fp32)
__device__ int    g_cnt[VMAX + 1];           // zero-init; re-zeroed in scan phase
__device__ int    g_off[VMAX + 1];
__device__ int    g_cur[VMAX];
__device__ __align__(16) int2 g_elist2[EMAX]; // {src*512, et*1024} byte offsets
__device__ float  g_agg[(size_t)VMAX * BD];  // 20 MB
__device__ __align__(16) __half g_xh[(size_t)VMAX * BD]; // fp16 x, TRANSPOSED [v][b*64+d]
__device__ int    g_tpart[256];              // lookback: tile aggregate + 1
__device__ int    g_tincl[256];              // lookback: tile inclusive + 1
__device__ int    g_done1, g_done2;          // grid barrier counters (reset by agg)

// ---------------- helpers ----------------
__device__ __forceinline__ void fma2(unsigned long long &d,
                                     unsigned long long a,
                                     unsigned long long b) {
    asm("fma.rn.f32x2 %0, %1, %2, %0;" : "+l"(d) : "l"(a), "l"(b));
}
__device__ __forceinline__ float2 unpack2(unsigned long long v) {
    float lo, hi;
    asm("mov.b64 {%0, %1}, %2;" : "=f"(lo), "=f"(hi) : "l"(v));
    return make_float2(lo, hi);
}
__device__ __forceinline__ int ldacq(const int* p) {
    int v;
    asm volatile("ld.acquire.gpu.s32 %0, [%1];" : "=r"(v) : "l"(p));
    return v;
}
__device__ __forceinline__ void strel(int* p, int v) {
    asm volatile("st.release.gpu.s32 [%0], %1;" :: "l"(p), "r"(v) : "memory");
}
__device__ __forceinline__ void grid_barrier(int* ctr, int target) {
    __syncthreads();
    if (threadIdx.x == 0) {
        __threadfence();
        atomicAdd(ctr, 1);
        while (ldacq(ctr) < target) { }
    }
    __syncthreads();
}

// =====================================================================
// kernel 1 (prep), 512 threads x PGRID (all resident, 32 warps/SM):
//   phase 1: rel GEMM (2 r/unit) + dst histogram + x->fp16 transpose
//   barrier; phase 2: lookback scan (512-wide tiles); barrier; phase 3: scatter
// =====================================================================
__global__ void __launch_bounds__(512, 2) prep_kernel(
    const float* __restrict__ z,  const float* __restrict__ Wz,
    const float* __restrict__ bz, const int* __restrict__ ei, int E,
    const float* __restrict__ x,  int V, int N4,
    int RU, int NC, int XC, int NB)
{
    __shared__ float zs[BD];
    __shared__ float wzt[2][64 * 65];
    int t = threadIdx.x;
    int TU = RU + NC + XC;

    // ---- phase 1: striped work units ----
    for (int u = blockIdx.x; u < TU; u += gridDim.x) {
        if (u < RU) {
            int h = t >> 8;           // half 0/1 -> relation r = 2u+h
            int tt = t & 255;
            int r = u * 2 + h;
            if (t < BD) zs[t] = z[t];
            for (int idx = tt; idx < 64 * 64; idx += 256) {
                int dd = idx >> 6, k = idx & 63;
                wzt[h][k * 65 + dd] = Wz[(r * 64 + dd) * 64 + k];
            }
            __syncthreads();
            int b = tt >> 6, d = tt & 63;
            float acc = bz[r * 64 + d];
#pragma unroll
            for (int k = 0; k < 64; k++)
                acc = fmaf(zs[b * 64 + k], wzt[h][k * 65 + d], acc);
            g_rel[r * BD + tt] = acc;
            __syncthreads();          // protect wzt against next unit's writes
        } else if (u < RU + NC) {
            int base = (u - RU) * 2048 + t;
#pragma unroll
            for (int k = 0; k < 4; k++) {
                int e = base + k * 512;
                if (e < E) atomicAdd(&g_cnt[ei[e * 3 + 2]], 1);
            }
        } else {
            // x (fp32 [b][v][d]) -> g_xh (fp16 TRANSPOSED [v][b*64+d])
            int base = (u - RU - NC) * 4096 + t;
            const float4* src = (const float4*)x;
#pragma unroll
            for (int k = 0; k < 8; k++) {
                int idx = base + k * 512;       // float4 index
                if (idx < N4) {
                    float4 f = src[idx];
                    int d4   = idx & 15;
                    int rest = idx >> 4;
                    int v    = rest % VMAX;
                    int b    = rest / VMAX;
                    __half2 h01 = __floats2half2_rn(f.x, f.y);
                    __half2 h23 = __floats2half2_rn(f.z, f.w);
                    uint2 o;
                    o.x = *(unsigned*)&h01;
                    o.y = *(unsigned*)&h23;
                    *(uint2*)(g_xh + (size_t)v * BD + b * 64 + d4 * 4) = o;
                }
            }
        }
    }

    grid_barrier(&g_done1, gridDim.x);

    // ---- phase 2: decoupled-lookback exclusive scan, 512-wide tiles ----
    if (blockIdx.x < NB) {
        __shared__ int ws[16];
        __shared__ int s_base;
        int lane = t & 31, w = t >> 5, bid = blockIdx.x;
        int i = bid * 512 + t;
        int c = (i < V) ? g_cnt[i] : 0;

        int inc = c;
#pragma unroll
        for (int o = 1; o < 32; o <<= 1) {
            int u2 = __shfl_up_sync(0xFFFFFFFFu, inc, o);
            if (lane >= o) inc += u2;
        }
        if (lane == 31) ws[w] = inc;
        __syncthreads();

        if (w == 0) {
            int v16 = (lane < 16) ? ws[lane] : 0;
            int sc = v16;
#pragma unroll
            for (int o = 1; o < 16; o <<= 1) {
                int u2 = __shfl_up_sync(0xFFFFFFFFu, sc, o);
                if (lane >= o) sc += u2;
            }
            int total = __shfl_sync(0xFFFFFFFFu, sc, 15);
            if (lane < 16) ws[lane] = sc - v16;
            if (lane == 0) strel(&g_tpart[bid], total + 1);

            int base = 0;
            int j = bid - 1;
            while (j >= 0) {
                int idx = j - lane;
                int iv = 0, pv = 0;
                if (idx >= 0) {
                    iv = ldacq(&g_tincl[idx]);
                    pv = ldacq(&g_tpart[idx]);
                }
                unsigned mi = __ballot_sync(0xFFFFFFFFu, iv != 0);
                unsigned mp = __ballot_sync(0xFFFFFFFFu, pv != 0);
                if (mi) {
                    int li = __ffs(mi) - 1;
                    unsigned need = (li == 0) ? 0u : ((1u << li) - 1u);
                    if ((mp & need) == need) {
                        int contrib = 0;
                        if (lane < li) contrib = pv - 1;
                        else if (lane == li) contrib = iv - 1;
#pragma unroll
                        for (int o = 16; o; o >>= 1)
                            contrib += __shfl_xor_sync(0xFFFFFFFFu, contrib, o);
                        base += contrib;
                        break;
                    }
                } else {
                    int wcount = (j + 1 < 32) ? (j + 1) : 32;
                    unsigned needall = (wcount == 32) ? 0xFFFFFFFFu
                                                      : ((1u << wcount) - 1u);
                    if ((mp & needall) == needall) {
                        int contrib = (idx >= 0) ? (pv - 1) : 0;
#pragma unroll
                        for (int o = 16; o; o >>= 1)
                            contrib += __shfl_xor_sync(0xFFFFFFFFu, contrib, o);
                        base += contrib;
                        j -= wcount;
                    }
                }
            }
            if (lane == 0) {
                s_base = base;
                strel(&g_tincl[bid], base + total + 1);
            }
        }
        __syncthreads();

        int base = s_base;
        if (i < V) {
            int excl = base + ws[w] + inc - c;
            g_off[i] = excl;
            g_cur[i] = excl;
            g_cnt[i] = 0;      // reset for next replay
        }
        if (bid == 0 && t == 0) g_off[V] = E;
    }

    grid_barrier(&g_done2, gridDim.x);

    // ---- phase 3: scatter (store precomputed byte offsets) ----
    for (int e = blockIdx.x * 512 + t; e < E; e += gridDim.x * 512) {
        int src = ei[e * 3 + 0];
        int et  = ei[e * 3 + 1];
        int dst = ei[e * 3 + 2];
        int p = atomicAdd(&g_cur[dst], 1);
        g_elist2[p] = make_int2(src << 9, et << 10);  // src*512B, et*1024B
    }
}

// =====================================================================
// kernel 2: aggregation. 1024 thr = 32 dst rows x 32 lanes, 2 blocks/SM.
// Node rows fp16 transposed (512B contiguous, LDG.128/lane);
// relation fp32 in 64 KB smem; elist carries byte offsets (no index ALU).
// Also resets prep's sync state for the next graph replay.
// =====================================================================
__global__ void __launch_bounds__(1024, 2) agg_kernel(int V) {
    if (blockIdx.x == 0) {
        if (threadIdx.x < 256) { g_tpart[threadIdx.x] = 0; g_tincl[threadIdx.x] = 0; }
        if (threadIdx.x == 0)  { g_done1 = 0; g_done2 = 0; }
    }
    extern __shared__ float rel_s[];    // 64 KB fp32 relation table
    for (int i = threadIdx.x; i < (Rc * BD) / 4; i += blockDim.x)
        ((float4*)rel_s)[i] = ((const float4*)g_rel)[i];
    __syncthreads();

    int ty = threadIdx.x >> 5;          // row slot 0..31
    int lane = threadIdx.x & 31;        // owns dims [lane*8, +8)
    const char* xbase = (const char*)g_xh + lane * 16;   // fp16: 8 dims = 16 B
    const char* rbase = (const char*)rel_s + lane * 32;  // fp32: 8 dims = 32 B

    for (int v = blockIdx.x * 32 + ty; v < V; v += gridDim.x * 32) {
        int s = g_off[v], e = g_off[v + 1];
        float a0 = 0.f, a1 = 0.f, a2 = 0.f, a3 = 0.f,
              a4 = 0.f, a5 = 0.f, a6 = 0.f, a7 = 0.f;
        int i = s;

#define EDGE(OS, OE)                                                          \
        {                                                                     \
            uint4  nh = *(const uint4*)(xbase + (OS));                        \
            float4 r0 = *(const float4*)(rbase + (OE));                       \
            float4 r1 = *(const float4*)(rbase + (OE) + 16);                  \
            float2 n01 = __half22float2(*(const __half2*)&nh.x);              \
            float2 n23 = __half22float2(*(const __half2*)&nh.y);              \
            float2 n45 = __half22float2(*(const __half2*)&nh.z);              \
            float2 n67 = __half22float2(*(const __half2*)&nh.w);              \
            a0 = fmaf(n01.x, r0.x, a0); a1 = fmaf(n01.y, r0.y, a1);           \
            a2 = fmaf(n23.x, r0.z, a2); a3 = fmaf(n23.y, r0.w, a3);           \
            a4 = fmaf(n45.x, r1.x, a4); a5 = fmaf(n45.y, r1.y, a5);           \
            a6 = fmaf(n67.x, r1.z, a6); a7 = fmaf(n67.y, r1.w, a7);           \
        }

        if (i < e && (i & 1)) {          // align to int4 (2-edge) granularity
            int2 p = g_elist2[i];
            EDGE(p.x, p.y);
            i++;
        }
        for (; i + 2 <= e; i += 2) {     // 2 edges per LDG.128 of elist
            int4 pp = *(const int4*)(&g_elist2[i]);
            EDGE(pp.x, pp.y);
            EDGE(pp.z, pp.w);
        }
        if (i < e) {
            int2 p = g_elist2[i];
            EDGE(p.x, p.y);
        }
#undef EDGE

        float* op = g_agg + (size_t)v * BD + lane * 8;
        *(float4*)(op)     = make_float4(a0, a1, a2, a3);
        *(float4*)(op + 4) = make_float4(a4, a5, a6, a7);
    }
}

// =====================================================================
// kernel 3: MLP (+beta*x, ReLU, LN, +x residual), 4 rows per barrier cycle
// =====================================================================
__global__ void __launch_bounds__(256) mlp_kernel(
    const float* __restrict__ x,
    const float* __restrict__ W1, const float* __restrict__ b1,
    const float* __restrict__ W2, const float* __restrict__ b2,
    const float* __restrict__ beta,
    const float* __restrict__ lnw, const float* __restrict__ lnb,
    float* __restrict__ out, int V)
{
    __shared__ __align__(16) float hsA[4][BD];
    __shared__ __align__(16) float hsB[4][BD];
    __shared__ float red[4][16];
    int t = threadIdx.x;
    int b = t >> 6, dq = t & 63;
    int warp = t >> 5, lane = t & 31;

    unsigned long long w1p[32], w2p[32];
    {
        const unsigned long long* W1q = (const unsigned long long*)(W1 + dq * 64);
        const unsigned long long* W2q = (const unsigned long long*)(W2 + dq * 64);
#pragma unroll
        for (int i = 0; i < 32; i++) { w1p[i] = W1q[i]; w2p[i] = W2q[i]; }
    }
    float b1r = b1[dq], b2r = b2[dq];
    float betar = beta[dq], lnwr = lnw[dq], lnbr = lnb[dq];

    const float* xb = x + (size_t)b * V * 64;
    float*       ob = out + (size_t)b * V * 64;

    int stride = gridDim.x * 4;
    int v0 = blockIdx.x * 4;
    float xvn[4], agn[4];
#pragma unroll
    for (int j = 0; j < 4; j++) {
        int vv = v0 + j;
        if (vv < V) { xvn[j] = xb[vv * 64 + dq]; agn[j] = g_agg[(size_t)vv * BD + t]; }
        else        { xvn[j] = 0.f;              agn[j] = 0.f; }
    }

    for (int v = v0; v < V; v += stride) {
        float xva[4];
#pragma unroll
        for (int j = 0; j < 4; j++) {
            xva[j] = xvn[j];
            hsA[j][t] = agn[j] + betar * xva[j];
        }
        int vn = v + stride;
#pragma unroll
        for (int j = 0; j < 4; j++) {
            int vv = vn + j;
            if (vv < V) { xvn[j] = xb[vv * 64 + dq]; agn[j] = g_agg[(size_t)vv * BD + t]; }
        }
        __syncthreads();

        unsigned long long a[8];
#pragma unroll
        for (int j = 0; j < 8; j++) a[j] = 0ull;
        {
            const ulonglong2* h0 = (const ulonglong2*)(hsA[0] + (b << 6));
            const ulonglong2* h1 = (const ulonglong2*)(hsA[1] + (b << 6));
            const ulonglong2* h2 = (const ulonglong2*)(hsA[2] + (b << 6));
            const ulonglong2* h3 = (const ulonglong2*)(hsA[3] + (b << 6));
#pragma unroll
            for (int i = 0; i < 16; i++) {
                ulonglong2 q0 = h0[i], q1 = h1[i], q2 = h2[i], q3 = h3[i];
                fma2(a[0], q0.x, w1p[2 * i]); fma2(a[1], q0.y, w1p[2 * i + 1]);
                fma2(a[2], q1.x, w1p[2 * i]); fma2(a[3], q1.y, w1p[2 * i + 1]);
                fma2(a[4], q2.x, w1p[2 * i]); fma2(a[5], q2.y, w1p[2 * i + 1]);
                fma2(a[6], q3.x, w1p[2 * i]); fma2(a[7], q3.y, w1p[2 * i + 1]);
            }
        }
#pragma unroll
        for (int j = 0; j < 4; j++) {
            float2 s0 = unpack2(a[2 * j]), s1 = unpack2(a[2 * j + 1]);
            hsB[j][t] = fmaxf(s0.x + s0.y + s1.x + s1.y + b1r, 0.f);
        }
        __syncthreads();

#pragma unroll
        for (int j = 0; j < 8; j++) a[j] = 0ull;
        {
            const ulonglong2* h0 = (const ulonglong2*)(hsB[0] + (b << 6));
            const ulonglong2* h1 = (const ulonglong2*)(hsB[1] + (b << 6));
            const ulonglong2* h2 = (const ulonglong2*)(hsB[2] + (b << 6));
            const ulonglong2* h3 = (const ulonglong2*)(hsB[3] + (b << 6));
#pragma unroll
            for (int i = 0; i < 16; i++) {
                ulonglong2 q0 = h0[i], q1 = h1[i], q2 = h2[i], q3 = h3[i];
                fma2(a[0], q0.x, w2p[2 * i]); fma2(a[1], q0.y, w2p[2 * i + 1]);
                fma2(a[2], q1.x, w2p[2 * i]); fma2(a[3], q1.y, w2p[2 * i + 1]);
                fma2(a[4], q2.x, w2p[2 * i]); fma2(a[5], q2.y, w2p[2 * i + 1]);
                fma2(a[6], q3.x, w2p[2 * i]); fma2(a[7], q3.y, w2p[2 * i + 1]);
            }
        }
        float a2[4], s[4], q[4];
#pragma unroll
        for (int j = 0; j < 4; j++) {
            float2 s0 = unpack2(a[2 * j]), s1 = unpack2(a[2 * j + 1]);
            a2[j] = s0.x + s0.y + s1.x + s1.y + b2r;
            s[j] = a2[j]; q[j] = a2[j] * a2[j];
        }
#pragma unroll
        for (int o = 16; o; o >>= 1) {
#pragma unroll
            for (int j = 0; j < 4; j++) {
                s[j] += __shfl_xor_sync(0xFFFFFFFFu, s[j], o);
                q[j] += __shfl_xor_sync(0xFFFFFFFFu, q[j], o);
            }
        }
        if (lane == 0) {
#pragma unroll
            for (int j = 0; j < 4; j++) {
                red[j][warp * 2] = s[j]; red[j][warp * 2 + 1] = q[j];
            }
        }
        __syncthreads();
#pragma unroll
        for (int j = 0; j < 4; j++) {
            if (v + j < V) {
                float st  = red[j][4 * b + 0] + red[j][4 * b + 2];
                float sqt = red[j][4 * b + 1] + red[j][4 * b + 3];
                float mu  = st * (1.f / 64.f);
                float var = sqt * (1.f / 64.f) - mu * mu;
                ob[(v + j) * 64 + dq] =
                    (a2[j] - mu) * rsqrtf(var + LN_EPS) * lnwr + lnbr + xva[j];
            }
        }
    }
}

// ---------------- launch ----------------
extern "C" void kernel_launch(void* const* d_in, const int* in_sizes, int n_in,
                              void* d_out, int out_size) {
    const float* x    = (const float*)d_in[0];
    const float* z    = (const float*)d_in[1];
    const int*   ei   = (const int*)  d_in[2];
    // d_in[3] = r_index (unused by reference)
    const float* Wz   = (const float*)d_in[4];
    const float* bz   = (const float*)d_in[5];
    const float* W1   = (const float*)d_in[6];
    const float* b1   = (const float*)d_in[7];
    const float* W2   = (const float*)d_in[8];
    const float* b2   = (const float*)d_in[9];
    const float* beta = (const float*)d_in[10];
    const float* lnw  = (const float*)d_in[11];
    const float* lnb  = (const float*)d_in[12];
    float* out = (float*)d_out;

    int E = in_sizes[2] / 3;
    int V = in_sizes[0] / (Bc * Dc);
    int NB = (V + 511) / 512;          // 40 scan tiles (<= PGRID, <= 256)
    int RU = Rc / 2;                   // 32 relation units (2 r each)
    int NC = (E + 2047) / 2048;        // histogram units (313)
    int N4 = (Bc * V * Dc) / 4;        // float4 count for convert (1.28M)
    int XC = (N4 + 4095) / 4096;       // convert units (313)

    prep_kernel<<<PGRID, 512>>>(z, Wz, bz, ei, E, x, V, N4, RU, NC, XC, NB);

    cudaFuncSetAttribute((const void*)agg_kernel,
                         cudaFuncAttributeMaxDynamicSharedMemorySize, 65536);
    agg_kernel<<<PGRID, 1024, 65536>>>(V);

    mlp_kernel<<<148, 256>>>(x, W1, b1, W2, b2, beta, lnw, lnb, out, V);
}

// round 11
// speedup vs baseline: 1.8498x; 1.8498x over previous
#include <cuda_runtime.h>
#include <cuda_fp16.h>
#include <cuda_bf16.h>

// Shapes (fixed for this problem): B=4, V=20000, D=64, R=64, E=640000
#define Bc   4
#define Dc   64
#define Rc   64
#define BD   256          // B*D
#define VMAX 20000
#define EMAX 640000
#define LN_EPS 1e-5f
#define PREPG 444         // prep grid; all-resident (3 blocks/SM x 148)
#define AGGG  296         // agg grid (2 blocks/SM)

// ---------------- device scratch (no allocations allowed) ----------------
__device__ float  g_rel[Rc * BD];            // relation[r][b*64+d] (64 KB, fp32)
__device__ int    g_cnt[VMAX + 1];           // zero-init; re-zeroed in scan phase
__device__ int    g_off[VMAX + 1];
__device__ int    g_cur[VMAX];
__device__ __align__(16) int2 g_elist2[EMAX]; // {src*512B, et*512B} byte offsets
__device__ float  g_agg[(size_t)VMAX * BD];  // 20 MB
__device__ __align__(16) __half g_xh[(size_t)VMAX * BD]; // fp16 x, TRANSPOSED [v][b*64+d]
__device__ int    g_tpart[256];              // lookback: tile aggregate + 1
__device__ int    g_tincl[256];              // lookback: tile inclusive + 1
__device__ int    g_done1, g_done2;          // grid barrier counters (reset by agg)

// ---------------- helpers ----------------
__device__ __forceinline__ void fma2(unsigned long long &d,
                                     unsigned long long a,
                                     unsigned long long b) {
    asm("fma.rn.f32x2 %0, %1, %2, %0;" : "+l"(d) : "l"(a), "l"(b));
}
__device__ __forceinline__ float2 unpack2(unsigned long long v) {
    float lo, hi;
    asm("mov.b64 {%0, %1}, %2;" : "=f"(lo), "=f"(hi) : "l"(v));
    return make_float2(lo, hi);
}
// half2 -> packed f32x2 in one u64
__device__ __forceinline__ unsigned long long h2f2(unsigned h2) {
    float2 f = __half22float2(*(__half2*)&h2);
    unsigned long long u;
    asm("mov.b64 %0, {%1, %2};" : "=l"(u) : "f"(f.x), "f"(f.y));
    return u;
}
__device__ __forceinline__ int ldacq(const int* p) {
    int v;
    asm volatile("ld.acquire.gpu.s32 %0, [%1];" : "=r"(v) : "l"(p));
    return v;
}
__device__ __forceinline__ void strel(int* p, int v) {
    asm volatile("st.release.gpu.s32 [%0], %1;" :: "l"(p), "r"(v) : "memory");
}
__device__ __forceinline__ void grid_barrier(int* ctr, int target) {
    __syncthreads();
    if (threadIdx.x == 0) {
        __threadfence();
        atomicAdd(ctr, 1);
        while (ldacq(ctr) < target) { }
    }
    __syncthreads();
}

// =====================================================================
// kernel 1 (prep), 256 threads x PREPG (3/SM, all resident):
//   phase 1: rel GEMM + dst histogram + x->fp16 transpose (striped units)
//   barrier; phase 2: lookback scan; barrier; phase 3: scatter
// =====================================================================
__global__ void __launch_bounds__(256, 3) prep_kernel(
    const float* __restrict__ z,  const float* __restrict__ Wz,
    const float* __restrict__ bz, const int* __restrict__ ei, int E,
    const float* __restrict__ x,  int V, int N4, int NC, int XC, int NB)
{
    __shared__ float zs[BD];
    __shared__ float wzt[64 * 65];
    int t = threadIdx.x;
    int TU = 64 + NC + XC;

    // ---- phase 1: striped work units ----
    // (each block executes at most ONE rel unit: u = bid only hits [0,64) once,
    //  so zs/wzt are written at most once per block -> no WAR hazard)
    for (int u = blockIdx.x; u < TU; u += gridDim.x) {
        if (u < 64) {
            int r = u;
            zs[t] = z[t];
            for (int idx = t; idx < 64 * 64; idx += 256) {
                int dd = idx >> 6, k = idx & 63;
                wzt[k * 65 + dd] = Wz[(r * 64 + dd) * 64 + k];
            }
            __syncthreads();
            int b = t >> 6, d = t & 63;
            float acc = bz[r * 64 + d];
#pragma unroll
            for (int k = 0; k < 64; k++)
                acc = fmaf(zs[b * 64 + k], wzt[k * 65 + d], acc);
            g_rel[r * BD + t] = acc;
        } else if (u < 64 + NC) {
            int base = (u - 64) * 1024 + t;
#pragma unroll
            for (int k = 0; k < 4; k++) {
                int e = base + k * 256;
                if (e < E) atomicAdd(&g_cnt[ei[e * 3 + 2]], 1);
            }
        } else {
            // x (fp32 [b][v][d]) -> g_xh (fp16 TRANSPOSED [v][b*64+d])
            int base = (u - 64 - NC) * 2048 + t;
            const float4* src = (const float4*)x;
#pragma unroll
            for (int k = 0; k < 8; k++) {
                int idx = base + k * 256;       // float4 index
                if (idx < N4) {
                    float4 f = src[idx];
                    int d4   = idx & 15;
                    int rest = idx >> 4;
                    int v    = rest % VMAX;
                    int b    = rest / VMAX;
                    __half2 h01 = __floats2half2_rn(f.x, f.y);
                    __half2 h23 = __floats2half2_rn(f.z, f.w);
                    uint2 o;
                    o.x = *(unsigned*)&h01;
                    o.y = *(unsigned*)&h23;
                    *(uint2*)(g_xh + (size_t)v * BD + b * 64 + d4 * 4) = o;
                }
            }
        }
    }

    grid_barrier(&g_done1, gridDim.x);

    // ---- phase 2: decoupled-lookback exclusive scan (blocks 0..NB-1) ----
    if (blockIdx.x < NB) {
        __shared__ int ws[8];
        __shared__ int s_base;
        int lane = t & 31, w = t >> 5, bid = blockIdx.x;
        int i = bid * 256 + t;
        int c = (i < V) ? g_cnt[i] : 0;

        int inc = c;
#pragma unroll
        for (int o = 1; o < 32; o <<= 1) {
            int u2 = __shfl_up_sync(0xFFFFFFFFu, inc, o);
            if (lane >= o) inc += u2;
        }
        if (lane == 31) ws[w] = inc;
        __syncthreads();

        if (w == 0) {
            int v8 = (lane < 8) ? ws[lane] : 0;
            int sc = v8;
#pragma unroll
            for (int o = 1; o < 8; o <<= 1) {
                int u2 = __shfl_up_sync(0xFFFFFFFFu, sc, o);
                if (lane >= o) sc += u2;
            }
            int total = __shfl_sync(0xFFFFFFFFu, sc, 7);
            if (lane < 8) ws[lane] = sc - v8;
            if (lane == 0) strel(&g_tpart[bid], total + 1);

            int base = 0;
            int j = bid - 1;
            while (j >= 0) {
                int idx = j - lane;
                int iv = 0, pv = 0;
                if (idx >= 0) {
                    iv = ldacq(&g_tincl[idx]);
                    pv = ldacq(&g_tpart[idx]);
                }
                unsigned mi = __ballot_sync(0xFFFFFFFFu, iv != 0);
                unsigned mp = __ballot_sync(0xFFFFFFFFu, pv != 0);
                if (mi) {
                    int li = __ffs(mi) - 1;
                    unsigned need = (li == 0) ? 0u : ((1u << li) - 1u);
                    if ((mp & need) == need) {
                        int contrib = 0;
                        if (lane < li) contrib = pv - 1;
                        else if (lane == li) contrib = iv - 1;
#pragma unroll
                        for (int o = 16; o; o >>= 1)
                            contrib += __shfl_xor_sync(0xFFFFFFFFu, contrib, o);
                        base += contrib;
                        break;
                    }
                } else {
                    int wcount = (j + 1 < 32) ? (j + 1) : 32;
                    unsigned needall = (wcount == 32) ? 0xFFFFFFFFu
                                                      : ((1u << wcount) - 1u);
                    if ((mp & needall) == needall) {
                        int contrib = (idx >= 0) ? (pv - 1) : 0;
#pragma unroll
                        for (int o = 16; o; o >>= 1)
                            contrib += __shfl_xor_sync(0xFFFFFFFFu, contrib, o);
                        base += contrib;
                        j -= wcount;
                    }
                }
            }
            if (lane == 0) {
                s_base = base;
                strel(&g_tincl[bid], base + total + 1);
            }
        }
        __syncthreads();

        int base = s_base;
        if (i < V) {
            int excl = base + ws[w] + inc - c;
            g_off[i] = excl;
            g_cur[i] = excl;
            g_cnt[i] = 0;      // reset for next replay
        }
        if (bid == 0 && t == 0) g_off[V] = E;
    }

    grid_barrier(&g_done2, gridDim.x);

    // ---- phase 3: scatter (store precomputed byte offsets) ----
    for (int e = blockIdx.x * 256 + t; e < E; e += gridDim.x * 256) {
        int src = ei[e * 3 + 0];
        int et  = ei[e * 3 + 1];
        int dst = ei[e * 3 + 2];
        int p = atomicAdd(&g_cur[dst], 1);
        g_elist2[p] = make_int2(src << 9, et << 9);  // src*512B, et*512B (fp16 rows)
    }
}

// =====================================================================
// kernel 2: aggregation. 1024 thr = 32 dst rows x 32 lanes, 2 blocks/SM.
// fp16 node rows (512B contiguous) + fp16 rel in 32 KB smem
// (16B lane stride -> conflict-free LDS.128). Byte-offset elist, FFMA2 accum.
// Also resets prep's sync state for the next graph replay.
// =====================================================================
__global__ void __launch_bounds__(1024, 2) agg_kernel(int V) {
    if (blockIdx.x == 0) {
        if (threadIdx.x < 256) { g_tpart[threadIdx.x] = 0; g_tincl[threadIdx.x] = 0; }
        if (threadIdx.x == 0)  { g_done1 = 0; g_done2 = 0; }
    }
    extern __shared__ __half rel_h[];   // 64 ets x 256 halfs = 32 KB
    for (int i = threadIdx.x; i < (Rc * BD) / 2; i += blockDim.x) {
        float2 f = ((const float2*)g_rel)[i];
        ((__half2*)rel_h)[i] = __floats2half2_rn(f.x, f.y);
    }
    __syncthreads();

    int ty = threadIdx.x >> 5;          // row slot 0..31
    int lane = threadIdx.x & 31;        // owns dims [lane*8, +8)
    const char* xbase = (const char*)g_xh  + lane * 16;   // 8 halfs = 16 B
    const char* rbase = (const char*)rel_h + lane * 16;   // 8 halfs = 16 B

    for (int v = blockIdx.x * 32 + ty; v < V; v += gridDim.x * 32) {
        int s = g_off[v], e = g_off[v + 1];
        unsigned long long A0 = 0ull, A1 = 0ull, A2 = 0ull, A3 = 0ull;
        int i = s;

#define EDGE(OS, OE)                                                          \
        {                                                                     \
            uint4 nh = *(const uint4*)(xbase + (OS));                         \
            uint4 rh = *(const uint4*)(rbase + (OE));                         \
            fma2(A0, h2f2(nh.x), h2f2(rh.x));                                 \
            fma2(A1, h2f2(nh.y), h2f2(rh.y));                                 \
            fma2(A2, h2f2(nh.z), h2f2(rh.z));                                 \
            fma2(A3, h2f2(nh.w), h2f2(rh.w));                                 \
        }

        if (i < e && (i & 1)) {          // align to int4 (2-edge) granularity
            int2 p = g_elist2[i];
            EDGE(p.x, p.y);
            i++;
        }
        for (; i + 2 <= e; i += 2) {     // 2 edges per broadcast LDG.128
            int4 pp = *(const int4*)(&g_elist2[i]);
            EDGE(pp.x, pp.y);
            EDGE(pp.z, pp.w);
        }
        if (i < e) {
            int2 p = g_elist2[i];
            EDGE(p.x, p.y);
        }
#undef EDGE

        float2 f0 = unpack2(A0), f1 = unpack2(A1), f2 = unpack2(A2), f3 = unpack2(A3);
        float* op = g_agg + (size_t)v * BD + lane * 8;
        *(float4*)(op)     = make_float4(f0.x, f0.y, f1.x, f1.y);
        *(float4*)(op + 4) = make_float4(f2.x, f2.y, f3.x, f3.y);
    }
}

// =====================================================================
// kernel 3: MLP (+beta*x, ReLU, LN, +x residual), 4 rows per barrier cycle
// =====================================================================
__global__ void __launch_bounds__(256) mlp_kernel(
    const float* __restrict__ x,
    const float* __restrict__ W1, const float* __restrict__ b1,
    const float* __restrict__ W2, const float* __restrict__ b2,
    const float* __restrict__ beta,
    const float* __restrict__ lnw, const float* __restrict__ lnb,
    float* __restrict__ out, int V)
{
    __shared__ __align__(16) float hsA[4][BD];
    __shared__ __align__(16) float hsB[4][BD];
    __shared__ float red[4][16];
    int t = threadIdx.x;
    int b = t >> 6, dq = t & 63;
    int warp = t >> 5, lane = t & 31;

    unsigned long long w1p[32], w2p[32];
    {
        const unsigned long long* W1q = (const unsigned long long*)(W1 + dq * 64);
        const unsigned long long* W2q = (const unsigned long long*)(W2 + dq * 64);
#pragma unroll
        for (int i = 0; i < 32; i++) { w1p[i] = W1q[i]; w2p[i] = W2q[i]; }
    }
    float b1r = b1[dq], b2r = b2[dq];
    float betar = beta[dq], lnwr = lnw[dq], lnbr = lnb[dq];

    const float* xb = x + (size_t)b * V * 64;
    float*       ob = out + (size_t)b * V * 64;

    int stride = gridDim.x * 4;
    int v0 = blockIdx.x * 4;
    float xvn[4], agn[4];
#pragma unroll
    for (int j = 0; j < 4; j++) {
        int vv = v0 + j;
        if (vv < V) { xvn[j] = xb[vv * 64 + dq]; agn[j] = g_agg[(size_t)vv * BD + t]; }
        else        { xvn[j] = 0.f;              agn[j] = 0.f; }
    }

    for (int v = v0; v < V; v += stride) {
        float xva[4];
#pragma unroll
        for (int j = 0; j < 4; j++) {
            xva[j] = xvn[j];
            hsA[j][t] = agn[j] + betar * xva[j];
        }
        int vn = v + stride;
#pragma unroll
        for (int j = 0; j < 4; j++) {
            int vv = vn + j;
            if (vv < V) { xvn[j] = xb[vv * 64 + dq]; agn[j] = g_agg[(size_t)vv * BD + t]; }
        }
        __syncthreads();

        unsigned long long a[8];
#pragma unroll
        for (int j = 0; j < 8; j++) a[j] = 0ull;
        {
            const ulonglong2* h0 = (const ulonglong2*)(hsA[0] + (b << 6));
            const ulonglong2* h1 = (const ulonglong2*)(hsA[1] + (b << 6));
            const ulonglong2* h2 = (const ulonglong2*)(hsA[2] + (b << 6));
            const ulonglong2* h3 = (const ulonglong2*)(hsA[3] + (b << 6));
#pragma unroll
            for (int i = 0; i < 16; i++) {
                ulonglong2 q0 = h0[i], q1 = h1[i], q2 = h2[i], q3 = h3[i];
                fma2(a[0], q0.x, w1p[2 * i]); fma2(a[1], q0.y, w1p[2 * i + 1]);
                fma2(a[2], q1.x, w1p[2 * i]); fma2(a[3], q1.y, w1p[2 * i + 1]);
                fma2(a[4], q2.x, w1p[2 * i]); fma2(a[5], q2.y, w1p[2 * i + 1]);
                fma2(a[6], q3.x, w1p[2 * i]); fma2(a[7], q3.y, w1p[2 * i + 1]);
            }
        }
#pragma unroll
        for (int j = 0; j < 4; j++) {
            float2 s0 = unpack2(a[2 * j]), s1 = unpack2(a[2 * j + 1]);
            hsB[j][t] = fmaxf(s0.x + s0.y + s1.x + s1.y + b1r, 0.f);
        }
        __syncthreads();

#pragma unroll
        for (int j = 0; j < 8; j++) a[j] = 0ull;
        {
            const ulonglong2* h0 = (const ulonglong2*)(hsB[0] + (b << 6));
            const ulonglong2* h1 = (const ulonglong2*)(hsB[1] + (b << 6));
            const ulonglong2* h2 = (const ulonglong2*)(hsB[2] + (b << 6));
            const ulonglong2* h3 = (const ulonglong2*)(hsB[3] + (b << 6));
#pragma unroll
            for (int i = 0; i < 16; i++) {
                ulonglong2 q0 = h0[i], q1 = h1[i], q2 = h2[i], q3 = h3[i];
                fma2(a[0], q0.x, w2p[2 * i]); fma2(a[1], q0.y, w2p[2 * i + 1]);
                fma2(a[2], q1.x, w2p[2 * i]); fma2(a[3], q1.y, w2p[2 * i + 1]);
                fma2(a[4], q2.x, w2p[2 * i]); fma2(a[5], q2.y, w2p[2 * i + 1]);
                fma2(a[6], q3.x, w2p[2 * i]); fma2(a[7], q3.y, w2p[2 * i + 1]);
            }
        }
        float a2[4], s[4], q[4];
#pragma unroll
        for (int j = 0; j < 4; j++) {
            float2 s0 = unpack2(a[2 * j]), s1 = unpack2(a[2 * j + 1]);
            a2[j] = s0.x + s0.y + s1.x + s1.y + b2r;
            s[j] = a2[j]; q[j] = a2[j] * a2[j];
        }
#pragma unroll
        for (int o = 16; o; o >>= 1) {
#pragma unroll
            for (int j = 0; j < 4; j++) {
                s[j] += __shfl_xor_sync(0xFFFFFFFFu, s[j], o);
                q[j] += __shfl_xor_sync(0xFFFFFFFFu, q[j], o);
            }
        }
        if (lane == 0) {
#pragma unroll
            for (int j = 0; j < 4; j++) {
                red[j][warp * 2] = s[j]; red[j][warp * 2 + 1] = q[j];
            }
        }
        __syncthreads();
#pragma unroll
        for (int j = 0; j < 4; j++) {
            if (v + j < V) {
                float st  = red[j][4 * b + 0] + red[j][4 * b + 2];
                float sqt = red[j][4 * b + 1] + red[j][4 * b + 3];
                float mu  = st * (1.f / 64.f);
                float var = sqt * (1.f / 64.f) - mu * mu;
                ob[(v + j) * 64 + dq] =
                    (a2[j] - mu) * rsqrtf(var + LN_EPS) * lnwr + lnbr + xva[j];
            }
        }
    }
}

// ---------------- launch ----------------
extern "C" void kernel_launch(void* const* d_in, const int* in_sizes, int n_in,
                              void* d_out, int out_size) {
    const float* x    = (const float*)d_in[0];
    const float* z    = (const float*)d_in[1];
    const int*   ei   = (const int*)  d_in[2];
    // d_in[3] = r_index (unused by reference)
    const float* Wz   = (const float*)d_in[4];
    const float* bz   = (const float*)d_in[5];
    const float* W1   = (const float*)d_in[6];
    const float* b1   = (const float*)d_in[7];
    const float* W2   = (const float*)d_in[8];
    const float* b2   = (const float*)d_in[9];
    const float* beta = (const float*)d_in[10];
    const float* lnw  = (const float*)d_in[11];
    const float* lnb  = (const float*)d_in[12];
    float* out = (float*)d_out;

    int E = in_sizes[2] / 3;
    int V = in_sizes[0] / (Bc * Dc);
    int NB = (V + 255) / 256;          // 79 scan tiles (<= PREPG, <= 256)
    int NC = (E + 1023) / 1024;        // histogram units (625)
    int N4 = (Bc * V * Dc) / 4;        // float4 count for convert (1.28M)
    int XC = (N4 + 2047) / 2048;       // convert units (625)

    prep_kernel<<<PREPG, 256>>>(z, Wz, bz, ei, E, x, V, N4, NC, XC, NB);
    agg_kernel<<<AGGG, 1024, 32768>>>(V);
    mlp_kernel<<<148, 256>>>(x, W1, b1, W2, b2, beta, lnw, lnb, out, V);
}

// round 14
// speedup vs baseline: 1.9041x; 1.0293x over previous
#include <cuda_runtime.h>
#include <cuda_fp16.h>
#include <cuda_bf16.h>

// Shapes (fixed for this problem): B=4, V=20000, D=64, R=64, E=640000
#define Bc   4
#define Dc   64
#define Rc   64
#define BD   256          // B*D
#define VMAX 20000
#define EMAX 640000
#define LN_EPS 1e-5f
#define PREPG 444         // prep grid; all-resident (3 blocks/SM x 148)
#define AGGG  296         // agg grid (512 thr, 2 blocks/SM)

// ---------------- device scratch (no allocations allowed) ----------------
__device__ float  g_rel[Rc * BD];            // relation[r][b*64+d] (64 KB, fp32)
__device__ int    g_cnt[VMAX + 1];           // zero-init; re-zeroed in scan phase
__device__ int    g_off[VMAX + 1];
__device__ int    g_cur[VMAX];
__device__ __align__(16) int2 g_elist2[EMAX]; // {src*512B, et*512B} byte offsets
__device__ float  g_agg[(size_t)VMAX * BD];  // 20 MB
__device__ __align__(16) __half g_xh[(size_t)VMAX * BD]; // fp16 x, TRANSPOSED [v][b*64+d]
__device__ int    g_tpart[256];              // lookback: tile aggregate + 1
__device__ int    g_tincl[256];              // lookback: tile inclusive + 1
__device__ int    g_done1, g_done2;          // grid barrier counters (reset by agg)

// ---------------- helpers ----------------
__device__ __forceinline__ void fma2(unsigned long long &d,
                                     unsigned long long a,
                                     unsigned long long b) {
    asm("fma.rn.f32x2 %0, %1, %2, %0;" : "+l"(d) : "l"(a), "l"(b));
}
__device__ __forceinline__ float2 unpack2(unsigned long long v) {
    float lo, hi;
    asm("mov.b64 {%0, %1}, %2;" : "=f"(lo), "=f"(hi) : "l"(v));
    return make_float2(lo, hi);
}
// half2 -> packed f32x2 in one u64
__device__ __forceinline__ unsigned long long h2f2(unsigned h2) {
    float2 f = __half22float2(*(__half2*)&h2);
    unsigned long long u;
    asm("mov.b64 %0, {%1, %2};" : "=l"(u) : "f"(f.x), "f"(f.y));
    return u;
}
__device__ __forceinline__ int ldacq(const int* p) {
    int v;
    asm volatile("ld.acquire.gpu.s32 %0, [%1];" : "=r"(v) : "l"(p));
    return v;
}
__device__ __forceinline__ void strel(int* p, int v) {
    asm volatile("st.release.gpu.s32 [%0], %1;" :: "l"(p), "r"(v) : "memory");
}
__device__ __forceinline__ void grid_barrier(int* ctr, int target) {
    __syncthreads();
    if (threadIdx.x == 0) {
        __threadfence();
        atomicAdd(ctr, 1);
        while (ldacq(ctr) < target) { }
    }
    __syncthreads();
}

// =====================================================================
// kernel 1 (prep), 256 threads x PREPG (3/SM, all resident):
//   phase 1: rel GEMM + dst histogram (4-edge int4 batches) + x->fp16
//   barrier; phase 2: lookback scan; barrier; phase 3: scatter (batched)
// =====================================================================
__global__ void __launch_bounds__(256, 3) prep_kernel(
    const float* __restrict__ z,  const float* __restrict__ Wz,
    const float* __restrict__ bz, const int* __restrict__ ei, int E,
    const float* __restrict__ x,  int V, int N4, int NC, int XC, int NB)
{
    __shared__ float zs[BD];
    __shared__ float wzt[64 * 65];
    int t = threadIdx.x;
    int TU = 64 + NC + XC;
    int E4 = E >> 2;                  // whole 4-edge groups

    // ---- phase 1: striped work units ----
    // (each block executes at most ONE rel unit -> zs/wzt written once/block)
    for (int u = blockIdx.x; u < TU; u += gridDim.x) {
        if (u < 64) {
            int r = u;
            zs[t] = z[t];
            for (int idx = t; idx < 64 * 64; idx += 256) {
                int dd = idx >> 6, k = idx & 63;
                wzt[k * 65 + dd] = Wz[(r * 64 + dd) * 64 + k];
            }
            __syncthreads();
            int b = t >> 6, d = t & 63;
            float acc = bz[r * 64 + d];
#pragma unroll
            for (int k = 0; k < 64; k++)
                acc = fmaf(zs[b * 64 + k], wzt[k * 65 + d], acc);
            g_rel[r * BD + t] = acc;
        } else if (u < 64 + NC) {
            // histogram: each thread takes one 4-edge group (3 aligned int4)
            int g = (u - 64) * 256 + t;          // group index
            if (g < E4) {
                const int4* p = (const int4*)(ei + g * 12);
                int4 a = p[0], b4 = p[1], c4 = p[2];
                atomicAdd(&g_cnt[a.z],  1);      // dst of edge 0 (word 2)
                atomicAdd(&g_cnt[b4.y], 1);      // word 5
                atomicAdd(&g_cnt[c4.x], 1);      // word 8
                atomicAdd(&g_cnt[c4.w], 1);      // word 11
            } else if (g == E4) {
                for (int e = E4 * 4; e < E; e++)
                    atomicAdd(&g_cnt[ei[e * 3 + 2]], 1);
            }
        } else {
            // x (fp32 [b][v][d]) -> g_xh (fp16 TRANSPOSED [v][b*64+d])
            int base = (u - 64 - NC) * 2048 + t;
            const float4* src = (const float4*)x;
#pragma unroll
            for (int k = 0; k < 8; k++) {
                int idx = base + k * 256;       // float4 index
                if (idx < N4) {
                    float4 f = src[idx];
                    int d4   = idx & 15;
                    int rest = idx >> 4;
                    int v    = rest % VMAX;
                    int b    = rest / VMAX;
                    __half2 h01 = __floats2half2_rn(f.x, f.y);
                    __half2 h23 = __floats2half2_rn(f.z, f.w);
                    uint2 o;
                    o.x = *(unsigned*)&h01;
                    o.y = *(unsigned*)&h23;
                    *(uint2*)(g_xh + (size_t)v * BD + b * 64 + d4 * 4) = o;
                }
            }
        }
    }

    grid_barrier(&g_done1, gridDim.x);

    // ---- phase 2: decoupled-lookback exclusive scan (blocks 0..NB-1) ----
    if (blockIdx.x < NB) {
        __shared__ int ws[8];
        __shared__ int s_base;
        int lane = t & 31, w = t >> 5, bid = blockIdx.x;
        int i = bid * 256 + t;
        int c = (i < V) ? g_cnt[i] : 0;

        int inc = c;
#pragma unroll
        for (int o = 1; o < 32; o <<= 1) {
            int u2 = __shfl_up_sync(0xFFFFFFFFu, inc, o);
            if (lane >= o) inc += u2;
        }
        if (lane == 31) ws[w] = inc;
        __syncthreads();

        if (w == 0) {
            int v8 = (lane < 8) ? ws[lane] : 0;
            int sc = v8;
#pragma unroll
            for (int o = 1; o < 8; o <<= 1) {
                int u2 = __shfl_up_sync(0xFFFFFFFFu, sc, o);
                if (lane >= o) sc += u2;
            }
            int total = __shfl_sync(0xFFFFFFFFu, sc, 7);
            if (lane < 8) ws[lane] = sc - v8;
            if (lane == 0) strel(&g_tpart[bid], total + 1);

            int base = 0;
            int j = bid - 1;
            while (j >= 0) {
                int idx = j - lane;
                int iv = 0, pv = 0;
                if (idx >= 0) {
                    iv = ldacq(&g_tincl[idx]);
                    pv = ldacq(&g_tpart[idx]);
                }
                unsigned mi = __ballot_sync(0xFFFFFFFFu, iv != 0);
                unsigned mp = __ballot_sync(0xFFFFFFFFu, pv != 0);
                if (mi) {
                    int li = __ffs(mi) - 1;
                    unsigned need = (li == 0) ? 0u : ((1u << li) - 1u);
                    if ((mp & need) == need) {
                        int contrib = 0;
                        if (lane < li) contrib = pv - 1;
                        else if (lane == li) contrib = iv - 1;
#pragma unroll
                        for (int o = 16; o; o >>= 1)
                            contrib += __shfl_xor_sync(0xFFFFFFFFu, contrib, o);
                        base += contrib;
                        break;
                    }
                } else {
                    int wcount = (j + 1 < 32) ? (j + 1) : 32;
                    unsigned needall = (wcount == 32) ? 0xFFFFFFFFu
                                                      : ((1u << wcount) - 1u);
                    if ((mp & needall) == needall) {
                        int contrib = (idx >= 0) ? (pv - 1) : 0;
#pragma unroll
                        for (int o = 16; o; o >>= 1)
                            contrib += __shfl_xor_sync(0xFFFFFFFFu, contrib, o);
                        base += contrib;
                        j -= wcount;
                    }
                }
            }
            if (lane == 0) {
                s_base = base;
                strel(&g_tincl[bid], base + total + 1);
            }
        }
        __syncthreads();

        int base = s_base;
        if (i < V) {
            int excl = base + ws[w] + inc - c;
            g_off[i] = excl;
            g_cur[i] = excl;
            g_cnt[i] = 0;      // reset for next replay
        }
        if (bid == 0 && t == 0) g_off[V] = E;
    }

    grid_barrier(&g_done2, gridDim.x);

    // ---- phase 3: scatter, 4 edges per thread-iter (batched loads+atomics) ----
    for (int g = blockIdx.x * 256 + t; g < E4; g += gridDim.x * 256) {
        const int4* p = (const int4*)(ei + g * 12);
        int4 a = p[0], b4 = p[1], c4 = p[2];
        // edges: {a.x,a.y,a.z} {a.w,b4.x,b4.y} {b4.z,b4.w,c4.x} {c4.y,c4.z,c4.w}
        int p0 = atomicAdd(&g_cur[a.z],  1);
        int p1 = atomicAdd(&g_cur[b4.y], 1);
        int p2 = atomicAdd(&g_cur[c4.x], 1);
        int p3 = atomicAdd(&g_cur[c4.w], 1);
        g_elist2[p0] = make_int2(a.x  << 9, a.y  << 9);
        g_elist2[p1] = make_int2(a.w  << 9, b4.x << 9);
        g_elist2[p2] = make_int2(b4.z << 9, b4.w << 9);
        g_elist2[p3] = make_int2(c4.y << 9, c4.z << 9);
    }
    if (blockIdx.x == 0 && t == 0) {
        for (int e = E4 * 4; e < E; e++) {
            int p = atomicAdd(&g_cur[ei[e * 3 + 2]], 1);
            g_elist2[p] = make_int2(ei[e * 3] << 9, ei[e * 3 + 1] << 9);
        }
    }
}

// =====================================================================
// kernel 2: aggregation. 512 thr = 16 dst rows x 32 lanes, 2 blocks/SM.
// 4-edge software pipeline: elist + all 4 node LDG.128 issued up front
// (MLP=4/warp), rel fp16 in 32 KB smem (conflict-free), FFMA2 accum.
// Also resets prep's sync state for the next graph replay.
// =====================================================================
__global__ void __launch_bounds__(512, 2) agg_kernel(int V) {
    if (blockIdx.x == 0) {
        if (threadIdx.x < 256) { g_tpart[threadIdx.x] = 0; g_tincl[threadIdx.x] = 0; }
        if (threadIdx.x == 0)  { g_done1 = 0; g_done2 = 0; }
    }
    extern __shared__ __half rel_h[];   // 64 ets x 256 halfs = 32 KB
    for (int i = threadIdx.x; i < (Rc * BD) / 2; i += blockDim.x) {
        float2 f = ((const float2*)g_rel)[i];
        ((__half2*)rel_h)[i] = __floats2half2_rn(f.x, f.y);
    }
    __syncthreads();

    int ty = threadIdx.x >> 5;          // row slot 0..15
    int lane = threadIdx.x & 31;        // owns dims [lane*8, +8)
    const char* xbase = (const char*)g_xh  + lane * 16;   // 8 halfs = 16 B
    const char* rbase = (const char*)rel_h + lane * 16;   // 8 halfs = 16 B

#define EDGE(NH, OE)                                                          \
        {                                                                     \
            uint4 rh = *(const uint4*)(rbase + (OE));                         \
            fma2(A0, h2f2((NH).x), h2f2(rh.x));                               \
            fma2(A1, h2f2((NH).y), h2f2(rh.y));                               \
            fma2(A2, h2f2((NH).z), h2f2(rh.z));                               \
            fma2(A3, h2f2((NH).w), h2f2(rh.w));                               \
        }

    for (int v = blockIdx.x * 16 + ty; v < V; v += gridDim.x * 16) {
        int s = g_off[v], e = g_off[v + 1];
        unsigned long long A0 = 0ull, A1 = 0ull, A2 = 0ull, A3 = 0ull;
        int i = s;

        // head: align to 4-edge granularity (also satisfies int4 alignment)
        for (; i < e && (i & 3); i++) {
            int2 p = g_elist2[i];
            uint4 nh = *(const uint4*)(xbase + p.x);
            EDGE(nh, p.y);
        }
        // 4-edge pipelined batches: all node loads in flight before converts
        for (; i + 4 <= e; i += 4) {
            int4 p01 = *(const int4*)(&g_elist2[i]);
            int4 p23 = *(const int4*)(&g_elist2[i + 2]);
            uint4 n0 = *(const uint4*)(xbase + p01.x);
            uint4 n1 = *(const uint4*)(xbase + p01.z);
            uint4 n2 = *(const uint4*)(xbase + p23.x);
            uint4 n3 = *(const uint4*)(xbase + p23.z);
            EDGE(n0, p01.y);
            EDGE(n1, p01.w);
            EDGE(n2, p23.y);
            EDGE(n3, p23.w);
        }
        // tail
        for (; i < e; i++) {
            int2 p = g_elist2[i];
            uint4 nh = *(const uint4*)(xbase + p.x);
            EDGE(nh, p.y);
        }

        float2 f0 = unpack2(A0), f1 = unpack2(A1), f2 = unpack2(A2), f3 = unpack2(A3);
        float* op = g_agg + (size_t)v * BD + lane * 8;
        *(float4*)(op)     = make_float4(f0.x, f0.y, f1.x, f1.y);
        *(float4*)(op + 4) = make_float4(f2.x, f2.y, f3.x, f3.y);
    }
#undef EDGE
}

// =====================================================================
// kernel 3: MLP (+beta*x, ReLU, LN, +x residual), 4 rows per barrier cycle
// =====================================================================
__global__ void __launch_bounds__(256) mlp_kernel(
    const float* __restrict__ x,
    const float* __restrict__ W1, const float* __restrict__ b1,
    const float* __restrict__ W2, const float* __restrict__ b2,
    const float* __restrict__ beta,
    const float* __restrict__ lnw, const float* __restrict__ lnb,
    float* __restrict__ out, int V)
{
    __shared__ __align__(16) float hsA[4][BD];
    __shared__ __align__(16) float hsB[4][BD];
    __shared__ float red[4][16];
    int t = threadIdx.x;
    int b = t >> 6, dq = t & 63;
    int warp = t >> 5, lane = t & 31;

    unsigned long long w1p[32], w2p[32];
    {
        const unsigned long long* W1q = (const unsigned long long*)(W1 + dq * 64);
        const unsigned long long* W2q = (const unsigned long long*)(W2 + dq * 64);
#pragma unroll
        for (int i = 0; i < 32; i++) { w1p[i] = W1q[i]; w2p[i] = W2q[i]; }
    }
    float b1r = b1[dq], b2r = b2[dq];
    float betar = beta[dq], lnwr = lnw[dq], lnbr = lnb[dq];

    const float* xb = x + (size_t)b * V * 64;
    float*       ob = out + (size_t)b * V * 64;

    int stride = gridDim.x * 4;
    int v0 = blockIdx.x * 4;
    float xvn[4], agn[4];
#pragma unroll
    for (int j = 0; j < 4; j++) {
        int vv = v0 + j;
        if (vv < V) { xvn[j] = xb[vv * 64 + dq]; agn[j] = g_agg[(size_t)vv * BD + t]; }
        else        { xvn[j] = 0.f;              agn[j] = 0.f; }
    }

    for (int v = v0; v < V; v += stride) {
        float xva[4];
#pragma unroll
        for (int j = 0; j < 4; j++) {
            xva[j] = xvn[j];
            hsA[j][t] = agn[j] + betar * xva[j];
        }
        int vn = v + stride;
#pragma unroll
        for (int j = 0; j < 4; j++) {
            int vv = vn + j;
            if (vv < V) { xvn[j] = xb[vv * 64 + dq]; agn[j] = g_agg[(size_t)vv * BD + t]; }
        }
        __syncthreads();

        unsigned long long a[8];
#pragma unroll
        for (int j = 0; j < 8; j++) a[j] = 0ull;
        {
            const ulonglong2* h0 = (const ulonglong2*)(hsA[0] + (b << 6));
            const ulonglong2* h1 = (const ulonglong2*)(hsA[1] + (b << 6));
            const ulonglong2* h2 = (const ulonglong2*)(hsA[2] + (b << 6));
            const ulonglong2* h3 = (const ulonglong2*)(hsA[3] + (b << 6));
#pragma unroll
            for (int i = 0; i < 16; i++) {
                ulonglong2 q0 = h0[i], q1 = h1[i], q2 = h2[i], q3 = h3[i];
                fma2(a[0], q0.x, w1p[2 * i]); fma2(a[1], q0.y, w1p[2 * i + 1]);
                fma2(a[2], q1.x, w1p[2 * i]); fma2(a[3], q1.y, w1p[2 * i + 1]);
                fma2(a[4], q2.x, w1p[2 * i]); fma2(a[5], q2.y, w1p[2 * i + 1]);
                fma2(a[6], q3.x, w1p[2 * i]); fma2(a[7], q3.y, w1p[2 * i + 1]);
            }
        }
#pragma unroll
        for (int j = 0; j < 4; j++) {
            float2 s0 = unpack2(a[2 * j]), s1 = unpack2(a[2 * j + 1]);
            hsB[j][t] = fmaxf(s0.x + s0.y + s1.x + s1.y + b1r, 0.f);
        }
        __syncthreads();

#pragma unroll
        for (int j = 0; j < 8; j++) a[j] = 0ull;
        {
            const ulonglong2* h0 = (const ulonglong2*)(hsB[0] + (b << 6));
            const ulonglong2* h1 = (const ulonglong2*)(hsB[1] + (b << 6));
            const ulonglong2* h2 = (const ulonglong2*)(hsB[2] + (b << 6));
            const ulonglong2* h3 = (const ulonglong2*)(hsB[3] + (b << 6));
#pragma unroll
            for (int i = 0; i < 16; i++) {
                ulonglong2 q0 = h0[i], q1 = h1[i], q2 = h2[i], q3 = h3[i];
                fma2(a[0], q0.x, w2p[2 * i]); fma2(a[1], q0.y, w2p[2 * i + 1]);
                fma2(a[2], q1.x, w2p[2 * i]); fma2(a[3], q1.y, w2p[2 * i + 1]);
                fma2(a[4], q2.x, w2p[2 * i]); fma2(a[5], q2.y, w2p[2 * i + 1]);
                fma2(a[6], q3.x, w2p[2 * i]); fma2(a[7], q3.y, w2p[2 * i + 1]);
            }
        }
        float a2[4], s[4], q[4];
#pragma unroll
        for (int j = 0; j < 4; j++) {
            float2 s0 = unpack2(a[2 * j]), s1 = unpack2(a[2 * j + 1]);
            a2[j] = s0.x + s0.y + s1.x + s1.y + b2r;
            s[j] = a2[j]; q[j] = a2[j] * a2[j];
        }
#pragma unroll
        for (int o = 16; o; o >>= 1) {
#pragma unroll
            for (int j = 0; j < 4; j++) {
                s[j] += __shfl_xor_sync(0xFFFFFFFFu, s[j], o);
                q[j] += __shfl_xor_sync(0xFFFFFFFFu, q[j], o);
            }
        }
        if (lane == 0) {
#pragma unroll
            for (int j = 0; j < 4; j++) {
                red[j][warp * 2] = s[j]; red[j][warp * 2 + 1] = q[j];
            }
        }
        __syncthreads();
#pragma unroll
        for (int j = 0; j < 4; j++) {
            if (v + j < V) {
                float st  = red[j][4 * b + 0] + red[j][4 * b + 2];
                float sqt = red[j][4 * b + 1] + red[j][4 * b + 3];
                float mu  = st * (1.f / 64.f);
                float var = sqt * (1.f / 64.f) - mu * mu;
                ob[(v + j) * 64 + dq] =
                    (a2[j] - mu) * rsqrtf(var + LN_EPS) * lnwr + lnbr + xva[j];
            }
        }
    }
}

// ---------------- launch ----------------
extern "C" void kernel_launch(void* const* d_in, const int* in_sizes, int n_in,
                              void* d_out, int out_size) {
    const float* x    = (const float*)d_in[0];
    const float* z    = (const float*)d_in[1];
    const int*   ei   = (const int*)  d_in[2];
    // d_in[3] = r_index (unused by reference)
    const float* Wz   = (const float*)d_in[4];
    const float* bz   = (const float*)d_in[5];
    const float* W1   = (const float*)d_in[6];
    const float* b1   = (const float*)d_in[7];
    const float* W2   = (const float*)d_in[8];
    const float* b2   = (const float*)d_in[9];
    const float* beta = (const float*)d_in[10];
    const float* lnw  = (const float*)d_in[11];
    const float* lnb  = (const float*)d_in[12];
    float* out = (float*)d_out;

    int E = in_sizes[2] / 3;
    int V = in_sizes[0] / (Bc * Dc);
    int NB = (V + 255) / 256;          // 79 scan tiles (<= PREPG, <= 256)
    int NC = ((E >> 2) + 256) / 256;   // histogram units (4-edge groups / 256)
    int N4 = (Bc * V * Dc) / 4;        // float4 count for convert (1.28M)
    int XC = (N4 + 2047) / 2048;       // convert units (625)

    prep_kernel<<<PREPG, 256>>>(z, Wz, bz, ei, E, x, V, N4, NC, XC, NB);
    agg_kernel<<<AGGG, 512, 32768>>>(V);
    mlp_kernel<<<148, 256>>>(x, W1, b1, W2, b2, beta, lnw, lnb, out, V);
}